// round 5
// baseline (speedup 1.0000x reference)
#include <cuda_runtime.h>
#include <cuda_fp16.h>
#include <stdint.h>

// ---------------------------------------------------------------------------
// Scratch for fp16-converted operands
// ---------------------------------------------------------------------------
#define H_CAP 1024
#define V_CAP 50000
#define M_CAP 1024
__device__ __half g_Wh[(size_t)V_CAP * H_CAP];   // ~100 MB
__device__ __half g_Ah[(size_t)M_CAP * H_CAP];   // 2 MB

// ---------------------------------------------------------------------------
// Tiling: CTA 256x256, 16 warps (4m x 4n), warp tile 64x64, 512 threads
// ---------------------------------------------------------------------------
#define TM 256
#define TN 256
#define KC 64            // fp16 K-chunk -> 128B rows (SW128 swizzle)
#define NTH 512
#define STAGES 3

#define SM_RED   0                      // 32 doubles (256B)
#define SM_MASK  256                    // 256 floats (1024B)
#define SM_LBL   1280                   // 256 int64 (2048B)
#define SM_PIPE  4096
#define ASTAGE   (TM * KC * 2)          // 32768 B
#define BSTAGE   (TN * KC * 2)          // 32768 B
#define STAGEB   (ASTAGE + BSTAGE)      // 65536 B
#define SMEM_TOTAL (SM_PIPE + STAGES * STAGEB)   // 200704 B (1 CTA/SM)

#define SWZ(off) ((off) ^ (((off) >> 3) & 0x70))

// ---------------------------------------------------------------------------
// PTX helpers (sm_80-baseline features: safe under compute_103 virtual arch)
// ---------------------------------------------------------------------------
__device__ __forceinline__ uint32_t smem_u32(const void* p) {
    uint32_t a;
    asm("{ .reg .u64 t; cvta.to.shared.u64 t, %1; cvt.u32.u64 %0, t; }" : "=r"(a) : "l"(p));
    return a;
}
__device__ __forceinline__ void cp16(uint32_t dst, const void* src, uint32_t srcbytes) {
    asm volatile("cp.async.cg.shared.global [%0], [%1], 16, %2;"
                 :: "r"(dst), "l"(src), "r"(srcbytes));
}
#define CP_COMMIT() asm volatile("cp.async.commit_group;" ::: "memory")
#define CP_WAIT(n)  asm volatile("cp.async.wait_group %0;" :: "n"(n) : "memory")

__device__ __forceinline__ void ldsm_x4(uint32_t* r, uint32_t addr) {
    asm volatile("ldmatrix.sync.aligned.m8n8.x4.shared.b16 {%0,%1,%2,%3}, [%4];"
                 : "=r"(r[0]), "=r"(r[1]), "=r"(r[2]), "=r"(r[3]) : "r"(addr));
}
__device__ __forceinline__ void mma16816(float* c, const uint32_t* a, uint32_t b0, uint32_t b1) {
    asm volatile(
        "mma.sync.aligned.m16n8k16.row.col.f32.f16.f16.f32 "
        "{%0,%1,%2,%3}, {%4,%5,%6,%7}, {%8,%9}, {%0,%1,%2,%3};"
        : "+f"(c[0]), "+f"(c[1]), "+f"(c[2]), "+f"(c[3])
        : "r"(a[0]), "r"(a[1]), "r"(a[2]), "r"(a[3]), "r"(b0), "r"(b1));
}

// ---------------------------------------------------------------------------
// Global loss accumulators
// ---------------------------------------------------------------------------
__device__ double g_sum_base;
__device__ double g_sum_gather;

__global__ void zero_acc_kernel() { g_sum_base = 0.0; g_sum_gather = 0.0; }

// ---------------------------------------------------------------------------
// fp32 -> fp16 conversion
// ---------------------------------------------------------------------------
__global__ void cvt_kernel(const float* __restrict__ s, __half* __restrict__ d, int n4) {
    int i = blockIdx.x * blockDim.x + threadIdx.x;
    if (i < n4) {
        float4 v = reinterpret_cast<const float4*>(s)[i];
        reinterpret_cast<__half2*>(d)[2 * i + 0] = __floats2half2_rn(v.x, v.y);
        reinterpret_cast<__half2*>(d)[2 * i + 1] = __floats2half2_rn(v.z, v.w);
    }
}

// ---------------------------------------------------------------------------
// Main GEMM + fused BCE-loss partials
//   logits[M,V] = A[M,H] @ W[V,H]^T  (fp16 inputs, fp32 accumulate)
// ---------------------------------------------------------------------------
__global__ void __launch_bounds__(NTH, 1)
spel_gemm_kernel(const long long* __restrict__ labels,
                 const float* __restrict__ attn_mask,
                 float* __restrict__ out,
                 int M, int H, int V, int write_logits) {
    extern __shared__ char smem[];
    const uint32_t sbase = smem_u32(smem);
    const int tid  = threadIdx.x;
    const int wid  = tid >> 5;
    const int lane = tid & 31;
    const int warp_m = wid >> 2;          // 0..3  (64 rows each)
    const int warp_n = wid & 3;           // 0..3  (64 cols each)
    const int m0 = blockIdx.x * TM;       // x fast: CTAs sharing a W tile adjacent
    const int n0 = blockIdx.y * TN;

    const __half* __restrict__ Ah = g_Ah;
    const __half* __restrict__ Wh = g_Wh;

    float acc[4][8][4];
    #pragma unroll
    for (int i = 0; i < 4; ++i)
        #pragma unroll
        for (int j = 0; j < 8; ++j)
            #pragma unroll
            for (int k = 0; k < 4; ++k) acc[i][j][k] = 0.f;

    const int NCH = H / KC;   // 16

    // ---- async tile loader: stage s <- K-chunk c ----
    auto load_chunk = [&](int s, int c) {
        const int k0 = c * KC;
        const uint32_t dA = sbase + SM_PIPE + s * STAGEB;
        const uint32_t dB = dA + ASTAGE;
        #pragma unroll
        for (int j = 0; j < 4; ++j) {                 // A: 256 rows x 8 segs
            int lin = tid + j * NTH;
            int row = lin >> 3, seg = lin & 7;
            cp16(dA + SWZ((uint32_t)(row * 128 + seg * 16)),
                 Ah + (size_t)(m0 + row) * H + k0 + seg * 8, 16u);
        }
        #pragma unroll
        for (int j = 0; j < 4; ++j) {                 // B: 256 rows x 8 segs (V guard)
            int lin = tid + j * NTH;
            int row = lin >> 3, seg = lin & 7;
            int gn = n0 + row;
            uint32_t sz = (gn < V) ? 16u : 0u;
            const __half* src = Wh + (size_t)((gn < V) ? gn : 0) * H + k0 + seg * 8;
            cp16(dB + SWZ((uint32_t)(row * 128 + seg * 16)), src, sz);
        }
    };

    // ---- prologue ----
    #pragma unroll
    for (int s = 0; s < STAGES - 1; ++s) {
        load_chunk(s, s);
        CP_COMMIT();
    }

    // lane-invariant ldmatrix address parts
    const int a_row  = warp_m * 64 + (lane & 15);
    const int a_khi  = (lane & 16) ? 8 : 0;
    const int b_row0 = warp_n * 64 + (lane & 7) + ((lane & 16) ? 8 : 0);
    const int b_khi  = (lane & 8) ? 8 : 0;

    // ---- mainloop ----
    int s_cons = 0, s_pf = STAGES - 1;
    for (int c = 0; c < NCH; ++c) {
        CP_WAIT(STAGES - 2);
        __syncthreads();
        int pf = c + STAGES - 1;
        if (pf < NCH) load_chunk(s_pf, pf);
        CP_COMMIT();
        if (++s_pf == STAGES) s_pf = 0;

        const uint32_t sA = sbase + SM_PIPE + s_cons * STAGEB;
        const uint32_t sB = sA + ASTAGE;
        if (++s_cons == STAGES) s_cons = 0;

        #pragma unroll
        for (int ks = 0; ks < KC / 16; ++ks) {
            const int kb = ks * 16;
            uint32_t af[4][4];
            #pragma unroll
            for (int mt = 0; mt < 4; ++mt)
                ldsm_x4(af[mt], sA + SWZ((uint32_t)((a_row + mt * 16) * 128 + (kb + a_khi) * 2)));
            uint32_t bf[4][4];
            #pragma unroll
            for (int h = 0; h < 4; ++h)
                ldsm_x4(bf[h], sB + SWZ((uint32_t)((b_row0 + h * 16) * 128 + (kb + b_khi) * 2)));
            #pragma unroll
            for (int mt = 0; mt < 4; ++mt) {
                #pragma unroll
                for (int nt = 0; nt < 8; ++nt) {
                    mma16816(acc[mt][nt], af[mt],
                             bf[nt >> 1][(nt & 1) * 2 + 0],
                             bf[nt >> 1][(nt & 1) * 2 + 1]);
                }
            }
        }
        __syncthreads();
    }
    CP_WAIT(0);
    __syncthreads();

    // ---- per-row mask / labels ----
    float*     msk_s = reinterpret_cast<float*>(smem + SM_MASK);
    long long* lbl_s = reinterpret_cast<long long*>(smem + SM_LBL);
    if (tid < TM) {
        int gm = m0 + tid;
        msk_s[tid] = (gm < M) ? attn_mask[gm] : 0.f;
        lbl_s[tid] = (gm < M) ? labels[gm] : (long long)(-1);
    }
    __syncthreads();

    // ---- epilogue in two 128-row halves (smem stage = pipeline region) ----
    float* stage = reinterpret_cast<float*>(smem + SM_PIPE);   // 128x256 f32 = 128KB
    float s_base = 0.f, s_g = 0.f;

    #pragma unroll
    for (int half = 0; half < 2; ++half) {
        // warps owning rows [half*128, half*128+128) store their accumulators
        if ((warp_m >> 1) == half) {
            const int g = lane >> 2;
            const int cpair = (lane & 3) * 2;
            const int rbase = (warp_m & 1) * 64;
            #pragma unroll
            for (int mt = 0; mt < 4; ++mt) {
                #pragma unroll
                for (int nt = 0; nt < 8; ++nt) {
                    int r = rbase + mt * 16 + g;
                    int cc = warp_n * 64 + nt * 8 + cpair;
                    stage[r * TN + cc]           = acc[mt][nt][0];
                    stage[r * TN + cc + 1]       = acc[mt][nt][1];
                    stage[(r + 8) * TN + cc]     = acc[mt][nt][2];
                    stage[(r + 8) * TN + cc + 1] = acc[mt][nt][3];
                }
            }
        }
        __syncthreads();

        const float4* stage4 = reinterpret_cast<const float4*>(stage);
        #pragma unroll 4
        for (int i = tid; i < 128 * TN / 4; i += NTH) {
            int r  = i >> 6;             // 64 float4 per row
            int c4 = (i & 63) << 2;
            int gn = n0 + c4;
            if (gn < V) {                // V%4==0 -> all-or-nothing per float4
                float4 v = stage4[i];
                int lr = half * 128 + r;
                int gm = m0 + lr;
                if (write_logits)
                    *reinterpret_cast<float4*>(out + (size_t)gm * V + gn) = v;
                float mk = msk_s[lr];
                float b0 = fmaxf(v.x, 0.f) + __logf(1.f + __expf(-fabsf(v.x)));
                float b1 = fmaxf(v.y, 0.f) + __logf(1.f + __expf(-fabsf(v.y)));
                float b2 = fmaxf(v.z, 0.f) + __logf(1.f + __expf(-fabsf(v.z)));
                float b3 = fmaxf(v.w, 0.f) + __logf(1.f + __expf(-fabsf(v.w)));
                s_base += (b0 + b1 + b2 + b3) * mk;
                if (mk > 0.f) {
                    long long lb = lbl_s[lr];
                    if (lb >= (long long)gn && lb < (long long)gn + 4) {
                        float xs[4] = {v.x, v.y, v.z, v.w};
                        s_g += xs[(int)(lb - gn)] * mk;
                    }
                }
            }
        }
        __syncthreads();   // stage free before next half overwrites
    }

    #pragma unroll
    for (int o = 16; o; o >>= 1) {
        s_base += __shfl_down_sync(0xFFFFFFFFu, s_base, o);
        s_g    += __shfl_down_sync(0xFFFFFFFFu, s_g, o);
    }
    double* red = reinterpret_cast<double*>(smem + SM_RED);
    if (lane == 0) { red[wid] = (double)s_base; red[16 + wid] = (double)s_g; }
    __syncthreads();
    if (tid == 0) {
        double tb = 0.0, tg = 0.0;
        #pragma unroll
        for (int w = 0; w < 16; ++w) { tb += red[w]; tg += red[16 + w]; }
        atomicAdd(&g_sum_base, tb);
        atomicAdd(&g_sum_gather, tg);
    }
}

// ---------------------------------------------------------------------------
// Finalize
// ---------------------------------------------------------------------------
__global__ void finalize_kernel(const float* __restrict__ attn_mask, int M,
                                float* __restrict__ out, long long loss_idx) {
    __shared__ float red[256];
    float s = 0.f;
    for (int i = threadIdx.x; i < M; i += 256) s += attn_mask[i];
    red[threadIdx.x] = s;
    __syncthreads();
    for (int o = 128; o; o >>= 1) {
        if (threadIdx.x < o) red[threadIdx.x] += red[threadIdx.x + o];
        __syncthreads();
    }
    if (threadIdx.x == 0) {
        double loss = (g_sum_base - g_sum_gather) / (double)red[0];
        out[loss_idx] = (float)loss;
    }
}

// ---------------------------------------------------------------------------
// kernel_launch
// ---------------------------------------------------------------------------
extern "C" void kernel_launch(void* const* d_in, const int* in_sizes, int n_in,
                              void* d_out, int out_size) {
    const float*     hidden = (const float*)d_in[0];
    const float*     W      = (const float*)d_in[1];
    const long long* labels = (const long long*)d_in[2];
    const float*     amask  = (const float*)d_in[3];
    float*           out    = (float*)d_out;

    const int M = in_sizes[2];              // B*T
    const int H = in_sizes[0] / M;
    const int V = in_sizes[1] / H;
    const long long LV = (long long)M * (long long)V;
    const int write_logits = ((long long)out_size >= LV) ? 1 : 0;

    cudaFuncSetAttribute(spel_gemm_kernel, cudaFuncAttributeMaxDynamicSharedMemorySize, SMEM_TOTAL);

    {
        __half* dW; cudaGetSymbolAddress((void**)&dW, g_Wh);
        __half* dA; cudaGetSymbolAddress((void**)&dA, g_Ah);
        int nW4 = in_sizes[1] / 4, nA4 = in_sizes[0] / 4;
        cvt_kernel<<<(nW4 + 255) / 256, 256>>>(W, dW, nW4);
        cvt_kernel<<<(nA4 + 255) / 256, 256>>>(hidden, dA, nA4);
    }

    zero_acc_kernel<<<1, 1>>>();

    dim3 grid((M + TM - 1) / TM, (V + TN - 1) / TN);
    spel_gemm_kernel<<<grid, NTH, SMEM_TOTAL>>>(labels, amask, out, M, H, V, write_logits);

    if ((long long)out_size != LV) {
        finalize_kernel<<<1, 256>>>(amask, M, out, (long long)out_size - 1);
    }
}

// round 6
// speedup vs baseline: 2.3683x; 2.3683x over previous
#include <cuda_runtime.h>
#include <cuda_fp16.h>
#include <stdint.h>

// ---------------------------------------------------------------------------
// Scratch for fp16-converted operands
// ---------------------------------------------------------------------------
#define H_CAP 1024
#define V_CAP 50000
#define M_CAP 1024
__device__ __half g_Wh[(size_t)V_CAP * H_CAP];   // ~100 MB
__device__ __half g_Ah[(size_t)M_CAP * H_CAP];   // 2 MB

// ---------------------------------------------------------------------------
// Tiling: CTA 128x256, 8 warps (2m x 4n), warp tile 64x64, 256 threads
// KC=128 split as 2 sub-tiles of 64 cols (128B rows keep SW128 valid)
// ---------------------------------------------------------------------------
#define TM 128
#define TN 256
#define KC 128
#define NTH 256
#define STAGES 2

#define SM_RED   0                      // 16 doubles
#define SM_MASK  256                    // 128 floats
#define SM_LBL   768                    // 128 int64
#define SM_PIPE  4096
#define ASUB     (TM * 128)             // 16384 B per 64-col sub-tile
#define BSUB     (TN * 128)             // 32768 B per sub-tile
#define ASTAGE   (2 * ASUB)             // 32768 B
#define BSTAGE   (2 * BSUB)             // 65536 B
#define STAGEB   (ASTAGE + BSTAGE)      // 98304 B
#define SMEM_TOTAL (SM_PIPE + STAGES * STAGEB)   // 200704 B (1 CTA/SM)

#define SWZ(off) ((off) ^ (((off) >> 3) & 0x70))

// ---------------------------------------------------------------------------
// PTX helpers (sm_80-baseline features: safe under compute_103 virtual arch)
// ---------------------------------------------------------------------------
__device__ __forceinline__ uint32_t smem_u32(const void* p) {
    uint32_t a;
    asm("{ .reg .u64 t; cvta.to.shared.u64 t, %1; cvt.u32.u64 %0, t; }" : "=r"(a) : "l"(p));
    return a;
}
__device__ __forceinline__ void cp16(uint32_t dst, const void* src, uint32_t srcbytes) {
    asm volatile("cp.async.cg.shared.global [%0], [%1], 16, %2;"
                 :: "r"(dst), "l"(src), "r"(srcbytes));
}
#define CP_COMMIT() asm volatile("cp.async.commit_group;" ::: "memory")
#define CP_WAIT(n)  asm volatile("cp.async.wait_group %0;" :: "n"(n) : "memory")

__device__ __forceinline__ void ldsm_x4(uint32_t* r, uint32_t addr) {
    asm volatile("ldmatrix.sync.aligned.m8n8.x4.shared.b16 {%0,%1,%2,%3}, [%4];"
                 : "=r"(r[0]), "=r"(r[1]), "=r"(r[2]), "=r"(r[3]) : "r"(addr));
}
__device__ __forceinline__ void mma16816(float* c, const uint32_t* a, uint32_t b0, uint32_t b1) {
    asm volatile(
        "mma.sync.aligned.m16n8k16.row.col.f32.f16.f16.f32 "
        "{%0,%1,%2,%3}, {%4,%5,%6,%7}, {%8,%9}, {%0,%1,%2,%3};"
        : "+f"(c[0]), "+f"(c[1]), "+f"(c[2]), "+f"(c[3])
        : "r"(a[0]), "r"(a[1]), "r"(a[2]), "r"(a[3]), "r"(b0), "r"(b1));
}

// ---------------------------------------------------------------------------
// Global loss accumulators
// ---------------------------------------------------------------------------
__device__ double g_sum_base;
__device__ double g_sum_gather;

__global__ void zero_acc_kernel() { g_sum_base = 0.0; g_sum_gather = 0.0; }

// ---------------------------------------------------------------------------
// fp32 -> fp16 conversion
// ---------------------------------------------------------------------------
__global__ void cvt_kernel(const float* __restrict__ s, __half* __restrict__ d, int n4) {
    int i = blockIdx.x * blockDim.x + threadIdx.x;
    if (i < n4) {
        float4 v = reinterpret_cast<const float4*>(s)[i];
        reinterpret_cast<__half2*>(d)[2 * i + 0] = __floats2half2_rn(v.x, v.y);
        reinterpret_cast<__half2*>(d)[2 * i + 1] = __floats2half2_rn(v.z, v.w);
    }
}

// ---------------------------------------------------------------------------
// Main GEMM + fused BCE-loss partials
//   logits[M,V] = A[M,H] @ W[V,H]^T  (fp16 inputs, fp32 accumulate)
// ---------------------------------------------------------------------------
__global__ void __launch_bounds__(NTH, 1)
spel_gemm_kernel(const long long* __restrict__ labels,
                 const float* __restrict__ attn_mask,
                 float* __restrict__ out,
                 int M, int H, int V, int write_logits) {
    extern __shared__ char smem[];
    const uint32_t sbase = smem_u32(smem);
    const int tid  = threadIdx.x;
    const int wid  = tid >> 5;
    const int lane = tid & 31;
    const int warp_m = wid >> 2;          // 0..1  (64 rows each)
    const int warp_n = wid & 3;           // 0..3  (64 cols each)
    const int m0 = blockIdx.x * TM;       // x fast: CTAs sharing a W tile adjacent
    const int n0 = blockIdx.y * TN;

    const __half* __restrict__ Ah = g_Ah;
    const __half* __restrict__ Wh = g_Wh;

    float acc[4][8][4];
    #pragma unroll
    for (int i = 0; i < 4; ++i)
        #pragma unroll
        for (int j = 0; j < 8; ++j)
            #pragma unroll
            for (int k = 0; k < 4; ++k) acc[i][j][k] = 0.f;

    const int NCH = H / KC;   // 8

    // ---- async tile loader: stage s <- K-chunk c (two 64-col sub-tiles) ----
    auto load_chunk = [&](int s, int c) {
        const int k0 = c * KC;
        const uint32_t dA = sbase + SM_PIPE + s * STAGEB;
        const uint32_t dB = dA + ASTAGE;
        #pragma unroll
        for (int j = 0; j < 8; ++j) {     // A: 2 subs x 128 rows x 8 segs = 2048
            int lin = tid + j * NTH;
            int sub = lin >> 10, rem = lin & 1023;
            int row = rem >> 3, seg = rem & 7;
            int gm = m0 + row;
            uint32_t sz = (gm < M) ? 16u : 0u;
            const __half* src = Ah + (size_t)((gm < M) ? gm : 0) * H + k0 + sub * 64 + seg * 8;
            cp16(dA + sub * ASUB + SWZ((uint32_t)(row * 128 + seg * 16)), src, sz);
        }
        #pragma unroll
        for (int j = 0; j < 16; ++j) {    // B: 2 subs x 256 rows x 8 segs = 4096
            int lin = tid + j * NTH;
            int sub = lin >> 11, rem = lin & 2047;
            int row = rem >> 3, seg = rem & 7;
            int gn = n0 + row;
            uint32_t sz = (gn < V) ? 16u : 0u;
            const __half* src = Wh + (size_t)((gn < V) ? gn : 0) * H + k0 + sub * 64 + seg * 8;
            cp16(dB + sub * BSUB + SWZ((uint32_t)(row * 128 + seg * 16)), src, sz);
        }
    };

    // ---- prologue ----
    load_chunk(0, 0);
    CP_COMMIT();

    // lane-invariant ldmatrix address parts
    const int a_row  = warp_m * 64 + (lane & 15);
    const int a_khi  = (lane & 16) ? 8 : 0;
    const int b_row0 = warp_n * 64 + (lane & 7) + ((lane & 16) ? 8 : 0);
    const int b_khi  = (lane & 8) ? 8 : 0;

    // ---- mainloop (2-stage: issue next load, then wait for current) ----
    int s = 0;
    for (int c = 0; c < NCH; ++c) {
        if (c + 1 < NCH) {                // buffer s^1 free: computed last iter
            load_chunk(s ^ 1, c + 1);
            CP_COMMIT();
            CP_WAIT(1);                   // chunk c landed; c+1 in flight
        } else {
            CP_WAIT(0);
        }
        __syncthreads();

        const uint32_t sA = sbase + SM_PIPE + s * STAGEB;
        const uint32_t sB = sA + ASTAGE;

        #pragma unroll
        for (int ks = 0; ks < KC / 16; ++ks) {   // 8 steps: sub = ks>>2
            const uint32_t subA = (uint32_t)(ks >> 2) * ASUB;
            const uint32_t subB = (uint32_t)(ks >> 2) * BSUB;
            const int kb = (ks & 3) * 16;
            uint32_t af[4][4];
            #pragma unroll
            for (int mt = 0; mt < 4; ++mt)
                ldsm_x4(af[mt], sA + subA + SWZ((uint32_t)((a_row + mt * 16) * 128 + (kb + a_khi) * 2)));
            uint32_t bf[4][4];
            #pragma unroll
            for (int h = 0; h < 4; ++h)
                ldsm_x4(bf[h], sB + subB + SWZ((uint32_t)((b_row0 + h * 16) * 128 + (kb + b_khi) * 2)));
            #pragma unroll
            for (int mt = 0; mt < 4; ++mt) {
                #pragma unroll
                for (int nt = 0; nt < 8; ++nt) {
                    mma16816(acc[mt][nt], af[mt],
                             bf[nt >> 1][(nt & 1) * 2 + 0],
                             bf[nt >> 1][(nt & 1) * 2 + 1]);
                }
            }
        }
        __syncthreads();                  // stage s reusable next iteration
        s ^= 1;
    }

    // ---- per-row mask / labels ----
    float*     msk_s = reinterpret_cast<float*>(smem + SM_MASK);
    long long* lbl_s = reinterpret_cast<long long*>(smem + SM_LBL);
    if (tid < TM) {
        int gm = m0 + tid;
        msk_s[tid] = (gm < M) ? attn_mask[gm] : 0.f;
        lbl_s[tid] = (gm < M) ? labels[gm] : (long long)(-1);
    }
    __syncthreads();

    // ---- epilogue straight from registers: float2 stores + loss partials ----
    float s_base = 0.f, s_g = 0.f;
    {
        const int g = lane >> 2;
        const int q = (lane & 3) * 2;
        #pragma unroll
        for (int mt = 0; mt < 4; ++mt) {
            #pragma unroll
            for (int half = 0; half < 2; ++half) {
                const int r = warp_m * 64 + mt * 16 + g + half * 8;
                const int gm = m0 + r;
                const float mk = msk_s[r];
                const long long lb = lbl_s[r];
                float* orow = out + (size_t)gm * V;
                #pragma unroll
                for (int nt = 0; nt < 8; ++nt) {
                    const int gn = n0 + warp_n * 64 + nt * 8 + q;
                    if (gn < V && gm < M) {       // V even -> pair all-or-nothing
                        const float x0 = acc[mt][nt][half * 2 + 0];
                        const float x1 = acc[mt][nt][half * 2 + 1];
                        if (write_logits)
                            *reinterpret_cast<float2*>(orow + gn) = make_float2(x0, x1);
                        float b0 = fmaxf(x0, 0.f) + __logf(1.f + __expf(-fabsf(x0)));
                        float b1 = fmaxf(x1, 0.f) + __logf(1.f + __expf(-fabsf(x1)));
                        s_base += (b0 + b1) * mk;
                        if (mk > 0.f) {
                            if (lb == (long long)gn)          s_g += x0 * mk;
                            else if (lb == (long long)gn + 1) s_g += x1 * mk;
                        }
                    }
                }
            }
        }
    }
    #pragma unroll
    for (int o = 16; o; o >>= 1) {
        s_base += __shfl_down_sync(0xFFFFFFFFu, s_base, o);
        s_g    += __shfl_down_sync(0xFFFFFFFFu, s_g, o);
    }
    double* red = reinterpret_cast<double*>(smem + SM_RED);
    if (lane == 0) { red[wid] = (double)s_base; red[8 + wid] = (double)s_g; }
    __syncthreads();
    if (tid == 0) {
        double tb = 0.0, tg = 0.0;
        #pragma unroll
        for (int w = 0; w < 8; ++w) { tb += red[w]; tg += red[8 + w]; }
        atomicAdd(&g_sum_base, tb);
        atomicAdd(&g_sum_gather, tg);
    }
}

// ---------------------------------------------------------------------------
// Finalize
// ---------------------------------------------------------------------------
__global__ void finalize_kernel(const float* __restrict__ attn_mask, int M,
                                float* __restrict__ out, long long loss_idx) {
    __shared__ float red[256];
    float s = 0.f;
    for (int i = threadIdx.x; i < M; i += 256) s += attn_mask[i];
    red[threadIdx.x] = s;
    __syncthreads();
    for (int o = 128; o; o >>= 1) {
        if (threadIdx.x < o) red[threadIdx.x] += red[threadIdx.x + o];
        __syncthreads();
    }
    if (threadIdx.x == 0) {
        double loss = (g_sum_base - g_sum_gather) / (double)red[0];
        out[loss_idx] = (float)loss;
    }
}

// ---------------------------------------------------------------------------
// kernel_launch
// ---------------------------------------------------------------------------
extern "C" void kernel_launch(void* const* d_in, const int* in_sizes, int n_in,
                              void* d_out, int out_size) {
    const float*     hidden = (const float*)d_in[0];
    const float*     W      = (const float*)d_in[1];
    const long long* labels = (const long long*)d_in[2];
    const float*     amask  = (const float*)d_in[3];
    float*           out    = (float*)d_out;

    const int M = in_sizes[2];              // B*T
    const int H = in_sizes[0] / M;
    const int V = in_sizes[1] / H;
    const long long LV = (long long)M * (long long)V;
    const int write_logits = ((long long)out_size >= LV) ? 1 : 0;

    cudaFuncSetAttribute(spel_gemm_kernel, cudaFuncAttributeMaxDynamicSharedMemorySize, SMEM_TOTAL);

    {
        __half* dW; cudaGetSymbolAddress((void**)&dW, g_Wh);
        __half* dA; cudaGetSymbolAddress((void**)&dA, g_Ah);
        int nW4 = in_sizes[1] / 4, nA4 = in_sizes[0] / 4;
        cvt_kernel<<<(nW4 + 255) / 256, 256>>>(W, dW, nW4);
        cvt_kernel<<<(nA4 + 255) / 256, 256>>>(hidden, dA, nA4);
    }

    zero_acc_kernel<<<1, 1>>>();

    dim3 grid((M + TM - 1) / TM, (V + TN - 1) / TN);
    spel_gemm_kernel<<<grid, NTH, SMEM_TOTAL>>>(labels, amask, out, M, H, V, write_logits);

    if ((long long)out_size != LV) {
        finalize_kernel<<<1, 256>>>(amask, M, out, (long long)out_size - 1);
    }
}

// round 7
// speedup vs baseline: 2.3788x; 1.0044x over previous
#include <cuda_runtime.h>
#include <cuda_fp16.h>
#include <stdint.h>

// ---------------------------------------------------------------------------
// Scratch for fp16-converted operands
// ---------------------------------------------------------------------------
#define H_CAP 1024
#define V_CAP 50000
#define M_CAP 1024
__device__ __half g_Wh[(size_t)V_CAP * H_CAP];   // ~100 MB
__device__ __half g_Ah[(size_t)M_CAP * H_CAP];   // 2 MB

// ---------------------------------------------------------------------------
// Tiling: CTA 128x256, 8 warps (2m x 4n), warp tile 64x64, 256 threads
// KC=128 split as 2 sub-tiles of 64 cols (128B rows keep SW128 valid)
// ---------------------------------------------------------------------------
#define TM 128
#define TN 256
#define KC 128
#define NTH 256
#define STAGES 2

#define SM_RED   0                      // 16 doubles
#define SM_MASK  256                    // 128 floats
#define SM_LBL   768                    // 128 int64
#define SM_PIPE  4096
#define ASUB     (TM * 128)             // 16384 B per 64-col sub-tile
#define BSUB     (TN * 128)             // 32768 B per sub-tile
#define ASTAGE   (2 * ASUB)             // 32768 B
#define BSTAGE   (2 * BSUB)             // 65536 B
#define STAGEB   (ASTAGE + BSTAGE)      // 98304 B
#define SMEM_TOTAL (SM_PIPE + STAGES * STAGEB)   // 200704 B (1 CTA/SM)

#define SWZ(off) ((off) ^ (((off) >> 3) & 0x70))

// ---------------------------------------------------------------------------
// PTX helpers (sm_80-baseline features: safe under compute_103 virtual arch)
// ---------------------------------------------------------------------------
__device__ __forceinline__ uint32_t smem_u32(const void* p) {
    uint32_t a;
    asm("{ .reg .u64 t; cvta.to.shared.u64 t, %1; cvt.u32.u64 %0, t; }" : "=r"(a) : "l"(p));
    return a;
}
__device__ __forceinline__ void cp16(uint32_t dst, const void* src, uint32_t srcbytes) {
    asm volatile("cp.async.cg.shared.global [%0], [%1], 16, %2;"
                 :: "r"(dst), "l"(src), "r"(srcbytes));
}
#define CP_COMMIT() asm volatile("cp.async.commit_group;" ::: "memory")
#define CP_WAIT(n)  asm volatile("cp.async.wait_group %0;" :: "n"(n) : "memory")

__device__ __forceinline__ void ldsm_x4(uint32_t* r, uint32_t addr) {
    asm volatile("ldmatrix.sync.aligned.m8n8.x4.shared.b16 {%0,%1,%2,%3}, [%4];"
                 : "=r"(r[0]), "=r"(r[1]), "=r"(r[2]), "=r"(r[3]) : "r"(addr));
}
__device__ __forceinline__ void mma16816(float* c, const uint32_t* a, uint32_t b0, uint32_t b1) {
    asm volatile(
        "mma.sync.aligned.m16n8k16.row.col.f32.f16.f16.f32 "
        "{%0,%1,%2,%3}, {%4,%5,%6,%7}, {%8,%9}, {%0,%1,%2,%3};"
        : "+f"(c[0]), "+f"(c[1]), "+f"(c[2]), "+f"(c[3])
        : "r"(a[0]), "r"(a[1]), "r"(a[2]), "r"(a[3]), "r"(b0), "r"(b1));
}

// ---------------------------------------------------------------------------
// Global loss accumulators
// ---------------------------------------------------------------------------
__device__ double g_sum_base;
__device__ double g_sum_gather;

__global__ void zero_acc_kernel() { g_sum_base = 0.0; g_sum_gather = 0.0; }

// ---------------------------------------------------------------------------
// fp32 -> fp16 conversion
// ---------------------------------------------------------------------------
__global__ void cvt_kernel(const float* __restrict__ s, __half* __restrict__ d, int n4) {
    int i = blockIdx.x * blockDim.x + threadIdx.x;
    if (i < n4) {
        float4 v = reinterpret_cast<const float4*>(s)[i];
        reinterpret_cast<__half2*>(d)[2 * i + 0] = __floats2half2_rn(v.x, v.y);
        reinterpret_cast<__half2*>(d)[2 * i + 1] = __floats2half2_rn(v.z, v.w);
    }
}

// ---------------------------------------------------------------------------
// Main GEMM + fused BCE-loss partials
//   logits[M,V] = A[M,H] @ W[V,H]^T  (fp16 inputs, fp32 accumulate)
// ---------------------------------------------------------------------------
__global__ void __launch_bounds__(NTH, 1)
spel_gemm_kernel(const long long* __restrict__ labels,
                 const float* __restrict__ attn_mask,
                 float* __restrict__ out,
                 int M, int H, int V, int write_logits) {
    extern __shared__ char smem[];
    const uint32_t sbase = smem_u32(smem);
    const int tid  = threadIdx.x;
    const int wid  = tid >> 5;
    const int lane = tid & 31;
    const int warp_m = wid >> 2;          // 0..1  (64 rows each)
    const int warp_n = wid & 3;           // 0..3  (64 cols each)
    const int m0 = blockIdx.x * TM;       // x fast: CTAs sharing a W tile adjacent
    const int n0 = blockIdx.y * TN;

    const __half* __restrict__ Ah = g_Ah;
    const __half* __restrict__ Wh = g_Wh;

    float acc[4][8][4];
    #pragma unroll
    for (int i = 0; i < 4; ++i)
        #pragma unroll
        for (int j = 0; j < 8; ++j)
            #pragma unroll
            for (int k = 0; k < 4; ++k) acc[i][j][k] = 0.f;

    const int NCH = H / KC;   // 8

    // ---- async tile loader: stage s <- K-chunk c (two 64-col sub-tiles) ----
    auto load_chunk = [&](int s, int c) {
        const int k0 = c * KC;
        const uint32_t dA = sbase + SM_PIPE + s * STAGEB;
        const uint32_t dB = dA + ASTAGE;
        #pragma unroll
        for (int j = 0; j < 8; ++j) {     // A: 2 subs x 128 rows x 8 segs = 2048
            int lin = tid + j * NTH;
            int sub = lin >> 10, rem = lin & 1023;
            int row = rem >> 3, seg = rem & 7;
            int gm = m0 + row;
            uint32_t sz = (gm < M) ? 16u : 0u;
            const __half* src = Ah + (size_t)((gm < M) ? gm : 0) * H + k0 + sub * 64 + seg * 8;
            cp16(dA + sub * ASUB + SWZ((uint32_t)(row * 128 + seg * 16)), src, sz);
        }
        #pragma unroll
        for (int j = 0; j < 16; ++j) {    // B: 2 subs x 256 rows x 8 segs = 4096
            int lin = tid + j * NTH;
            int sub = lin >> 11, rem = lin & 2047;
            int row = rem >> 3, seg = rem & 7;
            int gn = n0 + row;
            uint32_t sz = (gn < V) ? 16u : 0u;
            const __half* src = Wh + (size_t)((gn < V) ? gn : 0) * H + k0 + sub * 64 + seg * 8;
            cp16(dB + sub * BSUB + SWZ((uint32_t)(row * 128 + seg * 16)), src, sz);
        }
    };

    // ---- prologue ----
    load_chunk(0, 0);
    CP_COMMIT();

    // ---- per-warp constant swizzled offsets (SWZ + khi folded via XOR) ----
    // SWZ(row*128 + (kb+khi)*2) == (row*128 ^ ((row*16)&0x70) ^ khi*2) ^ kb*2
    const int a_row  = warp_m * 64 + (lane & 15);
    const int b_row0 = warp_n * 64 + (lane & 7) + ((lane & 16) ? 8 : 0);
    const uint32_t khiA2 = (lane & 16) ? 16u : 0u;
    const uint32_t khiB2 = (lane & 8)  ? 16u : 0u;
    uint32_t offA[4], offB[4];
    #pragma unroll
    for (int mt = 0; mt < 4; ++mt) {
        uint32_t R = (uint32_t)(a_row + mt * 16) * 128u;
        offA[mt] = R ^ ((R >> 3) & 0x70u) ^ khiA2;
    }
    #pragma unroll
    for (int h = 0; h < 4; ++h) {
        uint32_t R = (uint32_t)(b_row0 + h * 16) * 128u;
        offB[h] = R ^ ((R >> 3) & 0x70u) ^ khiB2;
    }

    uint32_t af[2][4][4], bf[2][4][4];

    // frag loader for k-step ks into buffer b
    auto load_frags = [&](int b, int ks, uint32_t sA, uint32_t sB) {
        const uint32_t kx = (uint32_t)(ks & 3) * 32u;       // kb*2
        const uint32_t aO = sA + (uint32_t)(ks >> 2) * ASUB;
        const uint32_t bO = sB + (uint32_t)(ks >> 2) * BSUB;
        #pragma unroll
        for (int mt = 0; mt < 4; ++mt) ldsm_x4(af[b][mt], aO + (offA[mt] ^ kx));
        #pragma unroll
        for (int h = 0; h < 4; ++h)    ldsm_x4(bf[b][h],  bO + (offB[h] ^ kx));
    };
    auto do_mmas = [&](int b) {
        #pragma unroll
        for (int mt = 0; mt < 4; ++mt) {
            #pragma unroll
            for (int nt = 0; nt < 8; ++nt) {
                mma16816(acc[mt][nt], af[b][mt],
                         bf[b][nt >> 1][(nt & 1) * 2 + 0],
                         bf[b][nt >> 1][(nt & 1) * 2 + 1]);
            }
        }
    };

    // ---- mainloop (2-stage cp.async; frag double-buffer inside chunk) ----
    int s = 0;
    for (int c = 0; c < NCH; ++c) {
        if (c + 1 < NCH) {                // buffer s^1 free: computed last iter
            load_chunk(s ^ 1, c + 1);
            CP_COMMIT();
            CP_WAIT(1);                   // chunk c landed; c+1 in flight
        } else {
            CP_WAIT(0);
        }
        __syncthreads();

        const uint32_t sA = sbase + SM_PIPE + s * STAGEB;
        const uint32_t sB = sA + ASTAGE;

        load_frags(0, 0, sA, sB);
        #pragma unroll
        for (int ks = 0; ks < KC / 16; ++ks) {
            if (ks < KC / 16 - 1) load_frags((ks + 1) & 1, ks + 1, sA, sB);
            do_mmas(ks & 1);
        }
        __syncthreads();                  // stage s reusable next iteration
        s ^= 1;
    }

    // ---- per-row mask / labels ----
    float*     msk_s = reinterpret_cast<float*>(smem + SM_MASK);
    long long* lbl_s = reinterpret_cast<long long*>(smem + SM_LBL);
    if (tid < TM) {
        int gm = m0 + tid;
        msk_s[tid] = (gm < M) ? attn_mask[gm] : 0.f;
        lbl_s[tid] = (gm < M) ? labels[gm] : (long long)(-1);
    }
    __syncthreads();

    // ---- epilogue straight from registers: float2 stores + loss partials ----
    float s_base = 0.f, s_g = 0.f;
    {
        const int g = lane >> 2;
        const int q = (lane & 3) * 2;
        #pragma unroll
        for (int mt = 0; mt < 4; ++mt) {
            #pragma unroll
            for (int half = 0; half < 2; ++half) {
                const int r = warp_m * 64 + mt * 16 + g + half * 8;
                const int gm = m0 + r;
                const float mk = msk_s[r];
                const long long lb = lbl_s[r];
                float* orow = out + (size_t)gm * V;
                #pragma unroll
                for (int nt = 0; nt < 8; ++nt) {
                    const int gn = n0 + warp_n * 64 + nt * 8 + q;
                    if (gn < V && gm < M) {       // V even -> pair all-or-nothing
                        const float x0 = acc[mt][nt][half * 2 + 0];
                        const float x1 = acc[mt][nt][half * 2 + 1];
                        if (write_logits)
                            *reinterpret_cast<float2*>(orow + gn) = make_float2(x0, x1);
                        float b0 = fmaxf(x0, 0.f) + __logf(1.f + __expf(-fabsf(x0)));
                        float b1 = fmaxf(x1, 0.f) + __logf(1.f + __expf(-fabsf(x1)));
                        s_base += (b0 + b1) * mk;
                        if (mk > 0.f) {
                            if (lb == (long long)gn)          s_g += x0 * mk;
                            else if (lb == (long long)gn + 1) s_g += x1 * mk;
                        }
                    }
                }
            }
        }
    }
    #pragma unroll
    for (int o = 16; o; o >>= 1) {
        s_base += __shfl_down_sync(0xFFFFFFFFu, s_base, o);
        s_g    += __shfl_down_sync(0xFFFFFFFFu, s_g, o);
    }
    double* red = reinterpret_cast<double*>(smem + SM_RED);
    if (lane == 0) { red[wid] = (double)s_base; red[8 + wid] = (double)s_g; }
    __syncthreads();
    if (tid == 0) {
        double tb = 0.0, tg = 0.0;
        #pragma unroll
        for (int w = 0; w < 8; ++w) { tb += red[w]; tg += red[8 + w]; }
        atomicAdd(&g_sum_base, tb);
        atomicAdd(&g_sum_gather, tg);
    }
}

// ---------------------------------------------------------------------------
// Finalize
// ---------------------------------------------------------------------------
__global__ void finalize_kernel(const float* __restrict__ attn_mask, int M,
                                float* __restrict__ out, long long loss_idx) {
    __shared__ float red[256];
    float s = 0.f;
    for (int i = threadIdx.x; i < M; i += 256) s += attn_mask[i];
    red[threadIdx.x] = s;
    __syncthreads();
    for (int o = 128; o; o >>= 1) {
        if (threadIdx.x < o) red[threadIdx.x] += red[threadIdx.x + o];
        __syncthreads();
    }
    if (threadIdx.x == 0) {
        double loss = (g_sum_base - g_sum_gather) / (double)red[0];
        out[loss_idx] = (float)loss;
    }
}

// ---------------------------------------------------------------------------
// kernel_launch
// ---------------------------------------------------------------------------
extern "C" void kernel_launch(void* const* d_in, const int* in_sizes, int n_in,
                              void* d_out, int out_size) {
    const float*     hidden = (const float*)d_in[0];
    const float*     W      = (const float*)d_in[1];
    const long long* labels = (const long long*)d_in[2];
    const float*     amask  = (const float*)d_in[3];
    float*           out    = (float*)d_out;

    const int M = in_sizes[2];              // B*T
    const int H = in_sizes[0] / M;
    const int V = in_sizes[1] / H;
    const long long LV = (long long)M * (long long)V;
    const int write_logits = ((long long)out_size >= LV) ? 1 : 0;

    cudaFuncSetAttribute(spel_gemm_kernel, cudaFuncAttributeMaxDynamicSharedMemorySize, SMEM_TOTAL);

    {
        __half* dW; cudaGetSymbolAddress((void**)&dW, g_Wh);
        __half* dA; cudaGetSymbolAddress((void**)&dA, g_Ah);
        int nW4 = in_sizes[1] / 4, nA4 = in_sizes[0] / 4;
        cvt_kernel<<<(nW4 + 255) / 256, 256>>>(W, dW, nW4);
        cvt_kernel<<<(nA4 + 255) / 256, 256>>>(hidden, dA, nA4);
    }

    zero_acc_kernel<<<1, 1>>>();

    dim3 grid((M + TM - 1) / TM, (V + TN - 1) / TN);
    spel_gemm_kernel<<<grid, NTH, SMEM_TOTAL>>>(labels, amask, out, M, H, V, write_logits);

    if ((long long)out_size != LV) {
        finalize_kernel<<<1, 256>>>(amask, M, out, (long long)out_size - 1);
    }
}